// round 16
// baseline (speedup 1.0000x reference)
#include <cuda_runtime.h>
#include <math.h>

#define BB 4
#define DD 64
#define NV (DD*DD*DD)        // 262144 voxels per batch
#define TOT (BB*NV)          // 1048576
#define NP 512               // points per batch
#define NCOL (TOT/64)        // 16384 z-columns
#define HSZ 1024             // rms hash slots
#define GRID 512             // persistent grid (co-resident: <=4 blocks/SM)
#define TPB 256
#define VPB (TOT/GRID)       // 2048 voxels per block (32 columns)

// -------- scratch (device globals: no allocations allowed) --------
__device__ double g_part[GRID];
__device__ unsigned int g_cnt1, g_cnt2;          // barrier counters (reset in k_rms)
__device__ int    g_parent[TOT];                 // -1 = background
__device__ unsigned long long g_colmask[NCOL];   // foreground bits per z-column
__device__ int    g_num[BB];                     // component count per batch

// -------- union-find: read-only find, min-link union -----------------------
__device__ __forceinline__ int uf_find(int i) {
    int p = g_parent[i];
    while (p != i) { i = p; p = g_parent[i]; }
    return i;
}

// returns 1 if this call demoted a root (at most once per call; exact forever)
__device__ __forceinline__ int uf_unite(int a, int b) {
    while (true) {
        a = uf_find(a);
        b = uf_find(b);
        if (a == b) return 0;
        if (a > b) { int t = a; a = b; b = t; }
        const int old = atomicMin(&g_parent[b], a);
        if (old == b) return 1;
        b = old;
    }
}

// run start of z-run containing bit z of mask m (bit z must be set)
__device__ __forceinline__ int run_start(unsigned long long m, int z) {
    const unsigned long long below =
        (z == 0) ? 0ull : (~m & ((1ull << z) - 1ull));
    return below ? (64 - __clzll(below)) : 0;
}

// spin until counter reaches GRID (callers arrive exactly once per replay)
__device__ __forceinline__ void arrive_and_spin(unsigned int* cnt) {
    __threadfence();
    atomicAdd(cnt, 1u);
    while (*(volatile unsigned int*)cnt < GRID) __nanosleep(64);
    __threadfence();
}

// -------- persistent kernel: sum -> mean -> init -> merge ------------------
__global__ void __launch_bounds__(TPB, 4) k_main(const float* __restrict__ x) {
    __shared__ double sh[TPB];
    __shared__ int s_runs, s_dem;
    const int t = threadIdx.x, bk = blockIdx.x;

    // ---- phase 1: fixed-order partial sum of this block's 2048 voxels ----
    {
        const float4* __restrict__ x4 = (const float4*)x + bk * (VPB / 4);
        const float4 a = x4[t * 2];
        const float4 b = x4[t * 2 + 1];
        sh[t] = (((double)a.x + (double)a.y) + ((double)a.z + (double)a.w))
              + (((double)b.x + (double)b.y) + ((double)b.z + (double)b.w));
    }
    __syncthreads();
    for (int o = 128; o > 0; o >>= 1) { if (t < o) sh[t] += sh[t + o]; __syncthreads(); }
    if (t == 0) {
        g_part[bk] = sh[0];
        if (bk == 0) { g_num[0] = 0; g_num[1] = 0; g_num[2] = 0; g_num[3] = 0; }
        arrive_and_spin(&g_cnt1);          // all partials + g_num zero visible after
    }
    __syncthreads();

    // ---- every block computes the SAME fixed-order final mean (L2-hot) ----
    sh[t] = g_part[t] + g_part[t + TPB];
    if (t == 0) { s_runs = 0; s_dem = 0; }
    __syncthreads();
    for (int o = 128; o > 0; o >>= 1) { if (t < o) sh[t] += sh[t + o]; __syncthreads(); }
    const float mean = (float)(sh[0] / (double)TOT);
    __syncthreads();

    // ---- phase 2: masks + run-start parents + run-count seed (L2-hot read) --
    // thread t: column c_local = t>>3 (32 cols/block), z-chunk k = t&7 (8 z each)
    const int c_local = t >> 3;
    const int k = t & 7;
    const int zb = k << 3;
    const int col = bk * 32 + c_local;

    unsigned long long m;
    {
        const float4* __restrict__ px =
            (const float4*)(x + (col << 6) + zb);
        const float4 v0 = px[0];
        const float4 v1 = px[1];
        unsigned int byte = 0;
        byte |= (v0.x > mean ? 1u : 0u);
        byte |= (v0.y > mean ? 2u : 0u);
        byte |= (v0.z > mean ? 4u : 0u);
        byte |= (v0.w > mean ? 8u : 0u);
        byte |= (v1.x > mean ? 16u : 0u);
        byte |= (v1.y > mean ? 32u : 0u);
        byte |= (v1.z > mean ? 64u : 0u);
        byte |= (v1.w > mean ? 128u : 0u);
        m = ((unsigned long long)byte) << (8 * k);
        m |= __shfl_xor_sync(0xFFFFFFFFu, m, 1);
        m |= __shfl_xor_sync(0xFFFFFFFFu, m, 2);
        m |= __shfl_xor_sync(0xFFFFFFFFu, m, 4);   // full 64-bit column mask
    }
    if (k == 0) {
        g_colmask[col] = m;
        const int nruns = __popcll(m & ~(m << 1));
        if (nruns) atomicAdd(&s_runs, nruns);
    }
    #pragma unroll
    for (int j = 0; j < 8; j++) {
        const int z = zb + j;
        g_parent[(col << 6) + z] =
            ((m >> z) & 1ull) ? ((col << 6) + run_start(m, z)) : -1;
    }
    __syncthreads();
    if (t == 0) {
        if (s_runs) atomicAdd(&g_num[bk >> 7], s_runs);   // block is batch-pure
        arrive_and_spin(&g_cnt2);          // all parents + masks visible after
    }
    __syncthreads();

    // ---- phase 3: merge; each thread owns its 8-z window, both dirs -------
    int dem = 0;
    {
        const int y = col & 63;
        const int x2 = (col >> 6) & 63;
        #pragma unroll
        for (int d = 0; d < 2; d++) {
            int nbr = -1;
            if (d == 0) { if (y > 0)  nbr = col - 1;  }
            else        { if (x2 > 0) nbr = col - 64; }
            if (nbr < 0) continue;
            const unsigned long long mB = __ldg(&g_colmask[nbr]);
            const unsigned long long ov = m & mB;
            unsigned int w = (unsigned int)((ov & ~(ov << 1)) >> zb) & 0xFFu;
            while (w) {
                const int z = zb + (__ffs(w) - 1);
                w &= w - 1;
                dem += uf_unite((col << 6) + run_start(m, z),
                                (nbr << 6) + run_start(mB, z));
            }
        }
    }
    if (dem) atomicAdd(&s_dem, dem);
    __syncthreads();
    if (t == 0 && s_dem)
        atomicSub(&g_num[bk >> 7], s_dem); // num = n_runs - n_demotions
}

// -------- point lookup + per-batch RMS (O(P) hash count) -------------------
__global__ void k_rms(const float* __restrict__ pts, float* __restrict__ out) {
    __shared__ int keys[HSZ];
    __shared__ int cnts[HSZ];
    __shared__ int s_sq, s_nc;
    const int b = blockIdx.x, t = threadIdx.x;

    if (b == 0 && t == 0) { g_cnt1 = 0; g_cnt2 = 0; }   // reset barriers for replay

    keys[t] = -1;           cnts[t] = 0;
    keys[t + NP] = -1;      cnts[t + NP] = 0;
    if (t == 0) { s_sq = 0; s_nc = 0; }

    const float* p = pts + (b * NP + t) * 3;
    const int s0 = (int)p[0];              // pts in [0, 64-1e-3): trunc == floor
    const int s1 = (int)p[1];
    const int s2 = (int)p[2];
    const int flat = (b << 18) + (s0 << 12) + (s1 << 6) + s2;
    const int pr = g_parent[flat];
    const int h = (pr >= 0) ? (uf_find(flat) + 1) : 0;
    __syncthreads();

    int my_slot = -1;
    if (h > 0) {
        unsigned int slot = ((unsigned int)h * 2654435761u) & (HSZ - 1);
        while (true) {
            const int kk = atomicCAS(&keys[slot], -1, h);
            if (kk == -1 || kk == h) {
                atomicAdd(&cnts[slot], 1);
                if (kk == -1) my_slot = (int)slot;
                break;
            }
            slot = (slot + 1) & (HSZ - 1);
        }
    }
    const int hits0 = __syncthreads_count(h == 0);   // also orders table writes

    if (my_slot >= 0) {
        const int d = cnts[my_slot] - 1;
        atomicAdd(&s_sq, d * d);           // (1-cnt)^2, exact in int
        atomicAdd(&s_nc, 1);
    }
    __syncthreads();

    if (t == 0) {
        const float num = (float)g_num[b];
        const float sq = (float)hits0 * (float)hits0
                       + (float)s_sq
                       + (num - (float)s_nc);   // unhit components
        out[b] = sqrtf(sq / (num + 1.0f));
    }
}

// -------- launcher ----------
extern "C" void kernel_launch(void* const* d_in, const int* in_sizes, int n_in,
                              void* d_out, int out_size) {
    const float* logits = (const float*)d_in[0];
    const float* pts    = (const float*)d_in[1];
    if (n_in >= 2 && in_sizes[0] != TOT) {   // defensive input-order check
        logits = (const float*)d_in[1];
        pts    = (const float*)d_in[0];
    }
    k_main<<<GRID, TPB>>>(logits);
    k_rms<<<BB, NP>>>(pts, (float*)d_out);
}

// round 17
// speedup vs baseline: 1.1421x; 1.1421x over previous
#include <cuda_runtime.h>
#include <math.h>

#define BB 4
#define DD 64
#define NV (DD*DD*DD)        // 262144 voxels per batch (2^18)
#define TOT (BB*NV)          // 1048576
#define NP 512               // points per batch
#define NCOL (TOT/64)        // 16384 z-columns
#define HSZ 1024             // hash slots (>= 2*NP)
#define RBLK 1024            // reduce grid

// -------- scratch (device globals: no allocations allowed) --------
__device__ double g_part[RBLK];
__device__ unsigned int g_arrived;               // last-block counter (self-resetting)
__device__ float  g_mean;
__device__ int    g_parent[TOT];                 // -1 = background
__device__ unsigned long long g_colmask[NCOL];   // foreground bits per z-column
__device__ int    g_num[BB];                     // component count per batch

// -------- 1) deterministic mean: single kernel, last-block finalize --------
__global__ void k_reduce(const float* __restrict__ x) {
    __shared__ double sh[256];
    __shared__ bool is_last;
    const int t = threadIdx.x, bk = blockIdx.x;
    // 1024 blocks x 256 threads x 1 float4 = full 1M floats
    {
        const float4 v = ((const float4*)x)[bk * 256 + t];
        sh[t] = ((double)v.x + (double)v.y) + ((double)v.z + (double)v.w);
    }
    __syncthreads();
    for (int o = 128; o > 0; o >>= 1) { if (t < o) sh[t] += sh[t + o]; __syncthreads(); }
    if (t == 0) {
        g_part[bk] = sh[0];
        __threadfence();
        is_last = (atomicAdd(&g_arrived, 1u) == RBLK - 1u);
    }
    __syncthreads();
    if (!is_last) return;

    // last block: fixed-order final reduction over 1024 partials (deterministic)
    double s = ((g_part[t] + g_part[t + 256]) + (g_part[t + 512] + g_part[t + 768]));
    sh[t] = s; __syncthreads();
    for (int o = 128; o > 0; o >>= 1) { if (t < o) sh[t] += sh[t + o]; __syncthreads(); }
    if (t == 0) {
        g_mean = (float)(sh[0] / (double)TOT);
        g_arrived = 0;                     // reset for next graph replay
        __threadfence();
    }
    if (t < BB) g_num[t] = 0;              // re-zero every replay
}

// -------- 2) init: z-run-start labels + column masks + run-count seed ------
// block = 256 threads = 4 columns x 64 z (batch-pure)
__global__ void k_init(const float* __restrict__ x) {
    __shared__ unsigned int shm[8];        // 8 half-column ballots
    __shared__ int s_runs;
    const int t = threadIdx.x;
    const int z = t & 63;
    const int col = blockIdx.x * 4 + (t >> 6);
    const int i = (col << 6) + z;

    if (t == 0) s_runs = 0;
    const bool fg = (x[i] > g_mean);
    const unsigned int b32 = __ballot_sync(0xFFFFFFFFu, fg);
    if ((t & 31) == 0) shm[t >> 5] = b32;
    __syncthreads();

    const int c = t >> 6;
    const unsigned long long m =
        (unsigned long long)shm[c * 2] |
        ((unsigned long long)shm[c * 2 + 1] << 32);

    if (fg) {
        const unsigned long long below =
            (z == 0) ? 0ull : (~m & ((1ull << z) - 1ull));
        const int start = below ? (64 - __clzll(below)) : 0;
        g_parent[i] = (col << 6) + start;
    } else {
        g_parent[i] = -1;
    }

    if (z == 0) {
        g_colmask[col] = m;
        const int nruns = __popcll(m & ~(m << 1));
        if (nruns) atomicAdd(&s_runs, nruns);
    }
    __syncthreads();
    if (t == 0 && s_runs)
        atomicAdd(&g_num[col >> 12], s_runs);   // one global atomic per block
}

// -------- union-find --------------------------------------------------------
// read-only find (merge phase: fastest measured variant, R6/R13)
__device__ __forceinline__ int uf_find(int i) {
    int p = g_parent[i];
    while (p != i) { i = p; p = g_parent[i]; }
    return i;
}

// halving find (rms phase): plain-store compression. Safe: writes only to
// nodes observed non-root; values strictly decrease and are valid ancestors;
// roots are never reverted. Result identical to read-only find.
__device__ __forceinline__ int uf_find_halve(int i) {
    int p = g_parent[i];
    while (p != i) {
        const int gp = g_parent[p];
        if (gp != p) g_parent[i] = gp;     // halving (benign race)
        i = p; p = gp;
    }
    return i;
}

// returns 1 if this call demoted a root (happens at most once per call)
__device__ __forceinline__ int uf_unite(int a, int b) {
    while (true) {
        a = uf_find(a);
        b = uf_find(b);
        if (a == b) return 0;
        if (a > b) { int t = a; a = b; b = t; }
        const int old = atomicMin(&g_parent[b], a);
        if (old == b) return 1;            // b was a root; demoted exactly once
        b = old;
    }
}

// run start of z-run containing bit z of mask m (bit z must be set)
__device__ __forceinline__ int run_start(unsigned long long m, int z) {
    const unsigned long long below =
        (z == 0) ? 0ull : (~m & ((1ull << z) - 1ull));
    return below ? (64 - __clzll(below)) : 0;
}

// -------- 3) merge: one thread per (voxel, x/y-dir); fused demote count ----
// blocks are batch-pure: i-range of 256 consecutive voxels, single dir.
__global__ void k_merge() {
    const int t = blockIdx.x * blockDim.x + threadIdx.x;
    const int i = t & (TOT - 1);
    const int dir = t >> 20;               // 0: -y, 1: -x
    const int z = i & 63;
    const int col = i >> 6;
    const int y = col & 63;
    const int x = (col >> 6) & 63;

    int demoted = 0;
    int nbr = -1;
    if (dir == 0) { if (y > 0) nbr = col - 1;  }
    else          { if (x > 0) nbr = col - 64; }

    if (nbr >= 0) {
        const unsigned long long mA = __ldg(&g_colmask[col]);
        const unsigned long long mB = __ldg(&g_colmask[nbr]);
        const unsigned long long ov = mA & mB;
        const bool edge = ((ov >> z) & 1ull) &&
                          !(z > 0 && ((ov >> (z - 1)) & 1ull));   // overlap-run start
        if (edge) {
            const int a = (col << 6) + run_start(mA, z);
            const int b = (nbr << 6) + run_start(mB, z);
            demoted = uf_unite(a, b);
        }
    }

    const int nblk = __syncthreads_count(demoted);
    if (threadIdx.x == 0 && nblk)
        atomicSub(&g_num[i >> 18], nblk);  // num = n_runs - n_demotions
}

// -------- 4) fused point lookup + per-batch RMS (O(P) hash count) ----------
__global__ void k_rms(const float* __restrict__ pts, float* __restrict__ out) {
    __shared__ int keys[HSZ];
    __shared__ int cnts[HSZ];
    __shared__ int s_sq, s_nc;
    const int b = blockIdx.x, t = threadIdx.x;

    // init hash table (each thread clears 2 slots)
    keys[t] = -1;           cnts[t] = 0;
    keys[t + NP] = -1;      cnts[t + NP] = 0;
    if (t == 0) { s_sq = 0; s_nc = 0; }

    const float* p = pts + (b * NP + t) * 3;
    const int s0 = (int)p[0];              // pts in [0, 64-1e-3): trunc == floor
    const int s1 = (int)p[1];
    const int s2 = (int)p[2];
    const int flat = (b << 18) + (s0 << 12) + (s1 << 6) + s2;
    const int pr = g_parent[flat];
    const int h = (pr >= 0) ? (uf_find_halve(flat) + 1) : 0;   // shared compression
    __syncthreads();

    // insert into hash table; remember if we own the slot (first inserter)
    int my_slot = -1;
    if (h > 0) {
        unsigned int slot = ((unsigned int)h * 2654435761u) & (HSZ - 1);
        while (true) {
            const int k = atomicCAS(&keys[slot], -1, h);
            if (k == -1 || k == h) {
                atomicAdd(&cnts[slot], 1);
                if (k == -1) my_slot = (int)slot;
                break;
            }
            slot = (slot + 1) & (HSZ - 1);
        }
    }
    const int hits0 = __syncthreads_count(h == 0);   // also orders table writes

    // slot owners contribute per-component terms
    if (my_slot >= 0) {
        const int d = cnts[my_slot] - 1;
        atomicAdd(&s_sq, d * d);           // (1-cnt)^2, exact in int
        atomicAdd(&s_nc, 1);
    }
    __syncthreads();

    if (t == 0) {
        const float num = (float)g_num[b];
        const float sq = (float)hits0 * (float)hits0
                       + (float)s_sq
                       + (num - (float)s_nc);   // unhit components
        out[b] = sqrtf(sq / (num + 1.0f));
    }
}

// -------- launcher ----------
extern "C" void kernel_launch(void* const* d_in, const int* in_sizes, int n_in,
                              void* d_out, int out_size) {
    const float* logits = (const float*)d_in[0];
    const float* pts    = (const float*)d_in[1];
    if (n_in >= 2 && in_sizes[0] != TOT) {   // defensive input-order check
        logits = (const float*)d_in[1];
        pts    = (const float*)d_in[0];
    }
    k_reduce<<<RBLK, 256>>>(logits);
    k_init<<<TOT / 256, 256>>>(logits);
    k_merge<<<(2 * TOT) / 256, 256>>>();
    k_rms<<<BB, NP>>>(pts, (float*)d_out);
}